// round 16
// baseline (speedup 1.0000x reference)
#include <cuda_runtime.h>
#include <cuda_bf16.h>
#include <cstdint>

// ---------------------------------------------------------------------------
// vGINMolEncoder: 5-layer GINEConv + virtual node, eval-mode BN, mean-pool.
// GEMMs: bf16x3 mma.sync.m16n8k16, templated N-tile (128 for Nc=600,
// 64 for Nc=300 to cut padded-column MMA waste). CSR edge aggregation.
// ---------------------------------------------------------------------------

#define MAXN 200000
#define MAXE 800000
#define MAXG 8000
#define DIM  300
#define HID  600
#define NLAYER 5
#define EPS_BN 1e-5f
#define C4 75            // DIM / 4
#define KPAD1 304        // DIM padded to 16
#define KPAD2 608        // HID padded to 16
#define SCAN_B 256

__device__ __align__(256) float g_h     [(size_t)MAXN * DIM];
__device__ __align__(256) float g_aggr  [(size_t)MAXN * DIM];
__device__ __align__(256) float g_hid   [(size_t)MAXN * HID];
__device__ __align__(256) float g_post  [(size_t)MAXN * DIM];
__device__ __align__(256) float g_vfeat [(size_t)MAXG * DIM];
__device__ __align__(256) float g_pooled[(size_t)MAXG * DIM];
__device__ __align__(256) float g_vhid  [(size_t)MAXG * HID];
__device__ __align__(256) float g_cnt   [MAXG];
// CSR scratch
__device__ __align__(256) int g_deg     [MAXN];
__device__ __align__(256) int g_rowstart[MAXN + 1];
__device__ __align__(256) int g_cursor  [MAXN];
__device__ __align__(256) int g_btot    [1024];
__device__ __align__(256) int g_eid     [MAXE];
// bf16 hi/lo split weights, transposed: [Nc][Kpad]
__device__ __align__(256) __nv_bfloat16 g_W1h [(size_t)NLAYER * HID * KPAD1];
__device__ __align__(256) __nv_bfloat16 g_W1l [(size_t)NLAYER * HID * KPAD1];
__device__ __align__(256) __nv_bfloat16 g_W2h [(size_t)NLAYER * DIM * KPAD2];
__device__ __align__(256) __nv_bfloat16 g_W2l [(size_t)NLAYER * DIM * KPAD2];
__device__ __align__(256) __nv_bfloat16 g_vW1h[(size_t)HID * KPAD1];
__device__ __align__(256) __nv_bfloat16 g_vW1l[(size_t)HID * KPAD1];
__device__ __align__(256) __nv_bfloat16 g_vW2h[(size_t)DIM * KPAD2];
__device__ __align__(256) __nv_bfloat16 g_vW2l[(size_t)DIM * KPAD2];

// ---------------------------------------------------------------------------
// CSR construction (once per call)
// ---------------------------------------------------------------------------
__global__ void deg_count_kernel(const int* __restrict__ dst, int* __restrict__ deg, int E) {
    int e = blockIdx.x * blockDim.x + threadIdx.x;
    if (e < E) atomicAdd(&deg[dst[e]], 1);
}

__global__ void scan_block_kernel(const int* __restrict__ deg, int* __restrict__ rs,
                                  int* __restrict__ btot, int N) {
    __shared__ int s[SCAN_B];
    int i = blockIdx.x * SCAN_B + threadIdx.x;
    int v = (i < N) ? deg[i] : 0;
    s[threadIdx.x] = v;
    __syncthreads();
#pragma unroll
    for (int off = 1; off < SCAN_B; off <<= 1) {
        int t = (threadIdx.x >= off) ? s[threadIdx.x - off] : 0;
        __syncthreads();
        s[threadIdx.x] += t;
        __syncthreads();
    }
    if (i < N) rs[i] = s[threadIdx.x] - v;
    if (threadIdx.x == SCAN_B - 1) btot[blockIdx.x] = s[threadIdx.x];
}

__global__ void scan_total_kernel(int* __restrict__ btot, int nb) {
    __shared__ int s[1024];
    int v = (threadIdx.x < nb) ? btot[threadIdx.x] : 0;
    s[threadIdx.x] = v;
    __syncthreads();
#pragma unroll
    for (int off = 1; off < 1024; off <<= 1) {
        int t = (threadIdx.x >= off) ? s[threadIdx.x - off] : 0;
        __syncthreads();
        s[threadIdx.x] += t;
        __syncthreads();
    }
    if (threadIdx.x < nb) btot[threadIdx.x] = s[threadIdx.x] - v;
}

__global__ void add_offsets_kernel(int* __restrict__ rs, const int* __restrict__ btot,
                                   int N, int E) {
    int i = blockIdx.x * blockDim.x + threadIdx.x;
    if (i < N) rs[i] += btot[i / SCAN_B];
    if (i == 0) rs[N] = E;
}

__global__ void scatter_kernel(const int* __restrict__ dst, int* __restrict__ cursor,
                               int* __restrict__ eid, int E) {
    int e = blockIdx.x * blockDim.x + threadIdx.x;
    if (e >= E) return;
    int p = atomicAdd(&cursor[dst[e]], 1);
    eid[p] = e;
}

// ---------------------------------------------------------------------------
// Elementwise kernels
// ---------------------------------------------------------------------------
__global__ void atom_encode_kernel(const int* __restrict__ x,
                                   const float* __restrict__ atom_emb,
                                   float* __restrict__ h, int N) {
    int idx = blockIdx.x * blockDim.x + threadIdx.x;
    if (idx >= N * C4) return;
    int n = idx / C4;
    int c = (idx - n * C4) * 4;
    float4 s = make_float4(0.f, 0.f, 0.f, 0.f);
#pragma unroll
    for (int f = 0; f < 9; f++) {
        int v = x[n * 9 + f];
        const float4 e = *(const float4*)(atom_emb + ((size_t)(f * 64 + v)) * DIM + c);
        s.x += e.x; s.y += e.y; s.z += e.z; s.w += e.w;
    }
    *(float4*)(h + (size_t)n * DIM + c) = s;
}

__global__ void edge_aggr_csr(const float* __restrict__ h,
                              const int* __restrict__ src,
                              const int* __restrict__ ea,
                              const float* __restrict__ bond_l,
                              const int* __restrict__ rs,
                              const int* __restrict__ eid,
                              float* __restrict__ aggr, int N) {
    int idx = blockIdx.x * blockDim.x + threadIdx.x;
    if (idx >= N * C4) return;
    int n = idx / C4;
    int c = (idx - n * C4) * 4;
    float4 s = *(const float4*)(h + (size_t)n * DIM + c);
    int b = rs[n], en = rs[n + 1];
    for (int i = b; i < en; i++) {
        int e  = eid[i];
        int sn = src[e];
        int a0 = ea[e * 3 + 0], a1 = ea[e * 3 + 1], a2 = ea[e * 3 + 2];
        const float4 b0 = *(const float4*)(bond_l + ((size_t)(0 * 16 + a0)) * DIM + c);
        const float4 b1 = *(const float4*)(bond_l + ((size_t)(1 * 16 + a1)) * DIM + c);
        const float4 b2 = *(const float4*)(bond_l + ((size_t)(2 * 16 + a2)) * DIM + c);
        const float4 hv = *(const float4*)(h + (size_t)sn * DIM + c);
        s.x += fmaxf(hv.x + b0.x + b1.x + b2.x, 0.f);
        s.y += fmaxf(hv.y + b0.y + b1.y + b2.y, 0.f);
        s.z += fmaxf(hv.z + b0.z + b1.z + b2.z, 0.f);
        s.w += fmaxf(hv.w + b0.w + b1.w + b2.w, 0.f);
    }
    *(float4*)(aggr + (size_t)n * DIM + c) = s;
}

__global__ void add_vfeat_kernel(const float* __restrict__ post,
                                 const float* __restrict__ vfeat,
                                 const int* __restrict__ batch,
                                 float* __restrict__ h, int N) {
    int idx = blockIdx.x * blockDim.x + threadIdx.x;
    if (idx >= N * C4) return;
    int n = idx / C4;
    int c = (idx - n * C4) * 4;
    int g = batch[n];
    const float4 p = *(const float4*)(post  + (size_t)n * DIM + c);
    const float4 v = *(const float4*)(vfeat + (size_t)g * DIM + c);
    float4 o = make_float4(p.x + v.x, p.y + v.y, p.z + v.z, p.w + v.w);
    *(float4*)(h + (size_t)n * DIM + c) = o;
}

__global__ void pool_kernel(const float* __restrict__ post,
                            const int* __restrict__ batch,
                            float* __restrict__ pooled, int N) {
    int idx = blockIdx.x * blockDim.x + threadIdx.x;
    if (idx >= N * C4) return;
    int n = idx / C4;
    int c = (idx - n * C4) * 4;
    int g = batch[n];
    const float4 p = *(const float4*)(post + (size_t)n * DIM + c);
    float* q = pooled + (size_t)g * DIM + c;
    atomicAdd(q + 0, p.x);
    atomicAdd(q + 1, p.y);
    atomicAdd(q + 2, p.z);
    atomicAdd(q + 3, p.w);
}

__global__ void count_kernel(const int* __restrict__ batch, float* __restrict__ cnt, int N) {
    int i = blockIdx.x * blockDim.x + threadIdx.x;
    if (i < N) atomicAdd(&cnt[batch[i]], 1.0f);
}

__global__ void vfeat_init_kernel(const float* __restrict__ vn, float* __restrict__ vfeat, int G) {
    int idx = blockIdx.x * blockDim.x + threadIdx.x;
    if (idx >= G * DIM) return;
    vfeat[idx] = vn[idx % DIM];
}

__global__ void copy_kernel(const float* __restrict__ src, float* __restrict__ dst, int n4) {
    int idx = blockIdx.x * blockDim.x + threadIdx.x;
    if (idx >= n4) return;
    *(float4*)(dst + idx * 4) = *(const float4*)(src + idx * 4);
}

__global__ void out_kernel(const float* __restrict__ pooled, const float* __restrict__ cnt,
                           float* __restrict__ out, int G) {
    int idx = blockIdx.x * blockDim.x + threadIdx.x;
    if (idx >= G * DIM) return;
    int g = idx / DIM;
    out[idx] = pooled[idx] / fmaxf(cnt[g], 1.0f);
}

__global__ void split_w_t(const float* __restrict__ W, __nv_bfloat16* __restrict__ Wh,
                          __nv_bfloat16* __restrict__ Wl, int K, int Nc, int Kpad) {
    int idx = blockIdx.x * blockDim.x + threadIdx.x;
    if (idx >= Nc * Kpad) return;
    int n = idx / Kpad;
    int k = idx - n * Kpad;
    float v = (k < K) ? W[(size_t)k * Nc + n] : 0.f;
    __nv_bfloat16 hh = __float2bfloat16_rn(v);
    __nv_bfloat16 ll = __float2bfloat16_rn(v - __bfloat162float(hh));
    Wh[idx] = hh;
    Wl[idx] = ll;
}

// ---------------------------------------------------------------------------
// bf16x3 GEMM, templated N-tile (TN = 128 or 64), fused BN(+ReLU) epilogue.
// C = epi(A @ W + bias). A:[M,K] fp32 rm; Wh/Wl:[Nc][Kpad] bf16 K-major.
// Block tile 128 x TN, K-tile 16, 256 threads (8 warps 4x2),
// warp tile 32 x TN/2, mma m16n8k16.
// ---------------------------------------------------------------------------
#define LDA 20
#define LDBH 24

__device__ __forceinline__ void cp_async16(uint32_t saddr, const void* gptr, int src_bytes) {
    asm volatile("cp.async.cg.shared.global [%0], [%1], 16, %2;\n"
                 :: "r"(saddr), "l"(gptr), "r"(src_bytes));
}
__device__ __forceinline__ void cp_commit() { asm volatile("cp.async.commit_group;\n" ::); }
template <int N>
__device__ __forceinline__ void cp_wait() { asm volatile("cp.async.wait_group %0;\n" :: "n"(N)); }

__device__ __forceinline__ void mma_bf16(float* d, const uint32_t* a, const uint32_t* b) {
    asm volatile(
        "mma.sync.aligned.m16n8k16.row.col.f32.bf16.bf16.f32 "
        "{%0,%1,%2,%3}, {%4,%5,%6,%7}, {%8,%9}, {%0,%1,%2,%3};\n"
        : "+f"(d[0]), "+f"(d[1]), "+f"(d[2]), "+f"(d[3])
        : "r"(a[0]), "r"(a[1]), "r"(a[2]), "r"(a[3]), "r"(b[0]), "r"(b[1]));
}

__device__ __forceinline__ void split_pack(float2 v, uint32_t& hi, uint32_t& lo) {
    __nv_bfloat16 hx = __float2bfloat16_rn(v.x), hy = __float2bfloat16_rn(v.y);
    __nv_bfloat16 lx = __float2bfloat16_rn(v.x - __bfloat162float(hx));
    __nv_bfloat16 ly = __float2bfloat16_rn(v.y - __bfloat162float(hy));
    __nv_bfloat162 H = __halves2bfloat162(hx, hy);
    __nv_bfloat162 L = __halves2bfloat162(lx, ly);
    hi = *(uint32_t*)&H;
    lo = *(uint32_t*)&L;
}

template <int TN>
__global__ __launch_bounds__(256) void gemm_bf16x3_bn(
    const float* __restrict__ A, const __nv_bfloat16* __restrict__ Bh,
    const __nv_bfloat16* __restrict__ Bl,
    const float* __restrict__ bias, const float* __restrict__ bnp,
    float* __restrict__ C, int M, int K, int Kpad, int Nc, int do_relu) {

    constexpr int NF = TN / 16;          // n-fragments per warp (8 or 4)
    __shared__ __align__(16) float         As [2][128][LDA];
    __shared__ __align__(16) __nv_bfloat16 BsH[2][TN][LDBH];
    __shared__ __align__(16) __nv_bfloat16 BsL[2][TN][LDBH];

    const int tid = threadIdx.x;
    const int w = tid >> 5, l = tid & 31;
    const int wm = (w & 3) * 32;
    const int wn = (w >> 2) * (TN / 2);
    const int m0 = blockIdx.y * 128;
    const int n0 = blockIdx.x * TN;
    const int iters = (K + 15) / 16;

    const int qr = l >> 2;
    const int qc = l & 3;

    const int a_row = tid >> 2;
    const int a_kc  = (tid & 3) * 4;
    const int b_row = tid >> 1;          // 0..127; valid rows < TN
    const int b_ck  = (tid & 1) * 8;
    const bool brok = (b_row < TN) && ((n0 + b_row) < Nc);
    const __nv_bfloat16* BhRow = Bh + (size_t)(brok ? n0 + b_row : 0) * Kpad;
    const __nv_bfloat16* BlRow = Bl + (size_t)(brok ? n0 + b_row : 0) * Kpad;

    float acc[2][NF][4];
#pragma unroll
    for (int mi = 0; mi < 2; mi++)
#pragma unroll
        for (int ni = 0; ni < NF; ni++)
#pragma unroll
            for (int r = 0; r < 4; r++) acc[mi][ni][r] = 0.f;

    auto issue_load = [&](int it, int buf) {
        const int k0 = it * 16;
#pragma unroll
        for (int i = 0; i < 2; i++) {
            int row = a_row + i * 64;
            int gm = m0 + row, gk = k0 + a_kc;
            int ok = (gm < M) && (gk + 4 <= K);
            const float* src = A + (size_t)(ok ? gm : 0) * K + (ok ? gk : 0);
            uint32_t dst = (uint32_t)__cvta_generic_to_shared(&As[buf][row][a_kc]);
            cp_async16(dst, src, ok ? 16 : 0);
        }
        if (b_row < TN) {
            uint32_t dsth = (uint32_t)__cvta_generic_to_shared(&BsH[buf][b_row][b_ck]);
            uint32_t dstl = (uint32_t)__cvta_generic_to_shared(&BsL[buf][b_row][b_ck]);
            cp_async16(dsth, BhRow + k0 + b_ck, brok ? 16 : 0);
            cp_async16(dstl, BlRow + k0 + b_ck, brok ? 16 : 0);
        }
        cp_commit();
    };

    issue_load(0, 0);

    for (int it = 0; it < iters; it++) {
        const int buf = it & 1;
        if (it + 1 < iters) {
            issue_load(it + 1, buf ^ 1);
            cp_wait<1>();
        } else {
            cp_wait<0>();
        }
        __syncthreads();

        uint32_t ah[2][4], al[2][4];
#pragma unroll
        for (int mi = 0; mi < 2; mi++) {
            int r0 = wm + mi * 16 + qr;
            split_pack(*(float2*)&As[buf][r0][2 * qc],         ah[mi][0], al[mi][0]);
            split_pack(*(float2*)&As[buf][r0 + 8][2 * qc],     ah[mi][1], al[mi][1]);
            split_pack(*(float2*)&As[buf][r0][2 * qc + 8],     ah[mi][2], al[mi][2]);
            split_pack(*(float2*)&As[buf][r0 + 8][2 * qc + 8], ah[mi][3], al[mi][3]);
        }
        uint32_t bh[NF][2], bl[NF][2];
#pragma unroll
        for (int ni = 0; ni < NF; ni++) {
            int n = wn + ni * 8 + qr;
            bh[ni][0] = *(const uint32_t*)&BsH[buf][n][2 * qc];
            bh[ni][1] = *(const uint32_t*)&BsH[buf][n][2 * qc + 8];
            bl[ni][0] = *(const uint32_t*)&BsL[buf][n][2 * qc];
            bl[ni][1] = *(const uint32_t*)&BsL[buf][n][2 * qc + 8];
        }
#pragma unroll
        for (int mi = 0; mi < 2; mi++)
#pragma unroll
            for (int ni = 0; ni < NF; ni++) {
                mma_bf16(acc[mi][ni], ah[mi], bl[ni]);
                mma_bf16(acc[mi][ni], al[mi], bh[ni]);
                mma_bf16(acc[mi][ni], ah[mi], bh[ni]);
            }
        __syncthreads();
    }

#pragma unroll
    for (int ni = 0; ni < NF; ni++) {
        int col = n0 + wn + ni * 8 + qc * 2;
        if (col >= Nc) continue;
        float bb0 = bias[col], bb1 = bias[col + 1];
        float ga0 = bnp[col],          be0 = bnp[Nc + col];
        float mu0 = bnp[2 * Nc + col], va0 = bnp[3 * Nc + col];
        float ga1 = bnp[col + 1],          be1 = bnp[Nc + col + 1];
        float mu1 = bnp[2 * Nc + col + 1], va1 = bnp[3 * Nc + col + 1];
        float s0 = ga0 * rsqrtf(va0 + EPS_BN), t0 = be0 - mu0 * s0;
        float s1 = ga1 * rsqrtf(va1 + EPS_BN), t1 = be1 - mu1 * s1;
#pragma unroll
        for (int mi = 0; mi < 2; mi++) {
#pragma unroll
            for (int r = 0; r < 2; r++) {
                int row = m0 + wm + mi * 16 + qr + r * 8;
                if (row >= M) continue;
                float v0 = (acc[mi][ni][r * 2 + 0] + bb0) * s0 + t0;
                float v1 = (acc[mi][ni][r * 2 + 1] + bb1) * s1 + t1;
                if (do_relu) { v0 = fmaxf(v0, 0.f); v1 = fmaxf(v1, 0.f); }
                *(float2*)(C + (size_t)row * Nc + col) = make_float2(v0, v1);
            }
        }
    }
}

static void run_gemm128(const float* A, const __nv_bfloat16* Bh, const __nv_bfloat16* Bl,
                        const float* bias, const float* bnp, float* C,
                        int M, int K, int Kpad, int Nc, int do_relu) {
    dim3 grid((Nc + 127) / 128, (M + 127) / 128);
    gemm_bf16x3_bn<128><<<grid, 256>>>(A, Bh, Bl, bias, bnp, C, M, K, Kpad, Nc, do_relu);
}
static void run_gemm64(const float* A, const __nv_bfloat16* Bh, const __nv_bfloat16* Bl,
                       const float* bias, const float* bnp, float* C,
                       int M, int K, int Kpad, int Nc, int do_relu) {
    dim3 grid((Nc + 63) / 64, (M + 127) / 128);
    gemm_bf16x3_bn<64><<<grid, 256>>>(A, Bh, Bl, bias, bnp, C, M, K, Kpad, Nc, do_relu);
}

// ---------------------------------------------------------------------------
// kernel_launch
// ---------------------------------------------------------------------------
extern "C" void kernel_launch(void* const* d_in, const int* in_sizes, int n_in,
                              void* d_out, int out_size) {
    const int*   x         = (const int*)  d_in[0];
    const int*   edge_idx  = (const int*)  d_in[1];
    const int*   edge_attr = (const int*)  d_in[2];
    const int*   batch     = (const int*)  d_in[3];
    const float* atom_emb  = (const float*)d_in[4];
    const float* bond_emb  = (const float*)d_in[5];
    const float* W1        = (const float*)d_in[6];
    const float* b1        = (const float*)d_in[7];
    const float* bn_in     = (const float*)d_in[8];
    const float* W2        = (const float*)d_in[9];
    const float* b2        = (const float*)d_in[10];
    const float* bn_out    = (const float*)d_in[11];
    const float* vn        = (const float*)d_in[12];
    const float* vW1       = (const float*)d_in[13];
    const float* vb1       = (const float*)d_in[14];
    const float* vbn1      = (const float*)d_in[15];
    const float* vW2       = (const float*)d_in[16];
    const float* vb2       = (const float*)d_in[17];
    const float* vbn2      = (const float*)d_in[18];
    float*       out       = (float*)d_out;

    const int N = in_sizes[0] / 9;
    const int E = in_sizes[1] / 2;
    const int G = out_size / DIM;

    float *h, *aggr, *hid, *post, *vfeat, *pooled, *vhid, *cnt;
    int *deg, *rowstart, *cursor, *btot, *eid;
    __nv_bfloat16 *W1h, *W1l, *W2h, *W2l, *vW1h, *vW1l, *vW2h, *vW2l;
    cudaGetSymbolAddress((void**)&h,        g_h);
    cudaGetSymbolAddress((void**)&aggr,     g_aggr);
    cudaGetSymbolAddress((void**)&hid,      g_hid);
    cudaGetSymbolAddress((void**)&post,     g_post);
    cudaGetSymbolAddress((void**)&vfeat,    g_vfeat);
    cudaGetSymbolAddress((void**)&pooled,   g_pooled);
    cudaGetSymbolAddress((void**)&vhid,     g_vhid);
    cudaGetSymbolAddress((void**)&cnt,      g_cnt);
    cudaGetSymbolAddress((void**)&deg,      g_deg);
    cudaGetSymbolAddress((void**)&rowstart, g_rowstart);
    cudaGetSymbolAddress((void**)&cursor,   g_cursor);
    cudaGetSymbolAddress((void**)&btot,     g_btot);
    cudaGetSymbolAddress((void**)&eid,      g_eid);
    cudaGetSymbolAddress((void**)&W1h,      g_W1h);
    cudaGetSymbolAddress((void**)&W1l,      g_W1l);
    cudaGetSymbolAddress((void**)&W2h,      g_W2h);
    cudaGetSymbolAddress((void**)&W2l,      g_W2l);
    cudaGetSymbolAddress((void**)&vW1h,     g_vW1h);
    cudaGetSymbolAddress((void**)&vW1l,     g_vW1l);
    cudaGetSymbolAddress((void**)&vW2h,     g_vW2h);
    cudaGetSymbolAddress((void**)&vW2l,     g_vW2l);

    const int* src = edge_idx;
    const int* dst = edge_idx + E;

    const int TPB = 256;
    const int nodeC4Blocks = (N * C4 + TPB - 1) / TPB;
    const int scanBlocks = (N + SCAN_B - 1) / SCAN_B;

    // ---- CSR build (once) ----
    cudaMemsetAsync(deg, 0, (size_t)N * sizeof(int));
    deg_count_kernel<<<(E + TPB - 1) / TPB, TPB>>>(dst, deg, E);
    scan_block_kernel<<<scanBlocks, SCAN_B>>>(deg, rowstart, btot, N);
    scan_total_kernel<<<1, 1024>>>(btot, scanBlocks);
    add_offsets_kernel<<<(N + TPB - 1) / TPB, TPB>>>(rowstart, btot, N, E);
    cudaMemcpyAsync(cursor, rowstart, (size_t)N * sizeof(int), cudaMemcpyDeviceToDevice);
    scatter_kernel<<<(E + TPB - 1) / TPB, TPB>>>(dst, cursor, eid, E);

    // ---- weight prep ----
    {
        int t1 = HID * KPAD1;
        int t2 = DIM * KPAD2;
        for (int l = 0; l < NLAYER; l++) {
            split_w_t<<<(t1 + TPB - 1) / TPB, TPB>>>(
                W1 + (size_t)l * DIM * HID, W1h + (size_t)l * t1, W1l + (size_t)l * t1,
                DIM, HID, KPAD1);
            split_w_t<<<(t2 + TPB - 1) / TPB, TPB>>>(
                W2 + (size_t)l * HID * DIM, W2h + (size_t)l * t2, W2l + (size_t)l * t2,
                HID, DIM, KPAD2);
        }
        split_w_t<<<(t1 + TPB - 1) / TPB, TPB>>>(vW1, vW1h, vW1l, DIM, HID, KPAD1);
        split_w_t<<<(t2 + TPB - 1) / TPB, TPB>>>(vW2, vW2h, vW2l, HID, DIM, KPAD2);
    }

    atom_encode_kernel<<<nodeC4Blocks, TPB>>>(x, atom_emb, h, N);
    vfeat_init_kernel<<<(G * DIM + TPB - 1) / TPB, TPB>>>(vn, vfeat, G);
    cudaMemsetAsync(cnt, 0, (size_t)G * sizeof(float));
    count_kernel<<<(N + TPB - 1) / TPB, TPB>>>(batch, cnt, N);

    for (int l = 0; l < NLAYER; l++) {
        if (l > 0)
            add_vfeat_kernel<<<nodeC4Blocks, TPB>>>(post, vfeat, batch, h, N);

        edge_aggr_csr<<<nodeC4Blocks, TPB>>>(
            h, src, edge_attr, bond_emb + (size_t)l * 3 * 16 * DIM,
            rowstart, eid, aggr, N);

        // hid = relu(bn_in(z @ W1 + b1))   [Nc=600 -> TN=128]
        run_gemm128(aggr, W1h + (size_t)l * HID * KPAD1, W1l + (size_t)l * HID * KPAD1,
                    b1 + (size_t)l * HID, bn_in + (size_t)l * 4 * HID, hid,
                    N, DIM, KPAD1, HID, 1);
        // post = bn_out(hid @ W2 + b2)     [Nc=300 -> TN=64]
        run_gemm64(hid, W2h + (size_t)l * DIM * KPAD2, W2l + (size_t)l * DIM * KPAD2,
                   b2 + (size_t)l * DIM, bn_out + (size_t)l * 4 * DIM, post,
                   N, HID, KPAD2, DIM, (l < NLAYER - 1) ? 1 : 0);

        if (l >= 1 && l < NLAYER - 1) {
            copy_kernel<<<(G * C4 + TPB - 1) / TPB, TPB>>>(vfeat, pooled, G * C4);
            pool_kernel<<<nodeC4Blocks, TPB>>>(post, batch, pooled, N);
            run_gemm128(pooled, vW1h, vW1l, vb1, vbn1, vhid, G, DIM, KPAD1, HID, 1);
            run_gemm64(vhid, vW2h, vW2l, vb2, vbn2, vfeat, G, HID, KPAD2, DIM, 1);
        }
    }

    cudaMemsetAsync(pooled, 0, (size_t)G * DIM * sizeof(float));
    pool_kernel<<<nodeC4Blocks, TPB>>>(post, batch, pooled, N);
    out_kernel<<<(G * DIM + TPB - 1) / TPB, TPB>>>(pooled, cnt, out, G);
}

// round 17
// speedup vs baseline: 1.0159x; 1.0159x over previous
#include <cuda_runtime.h>
#include <cuda_bf16.h>
#include <cstdint>

// ---------------------------------------------------------------------------
// vGINMolEncoder: 5-layer GINEConv + virtual node, eval-mode BN, mean-pool.
// GEMMs: bf16x3 mma.sync.m16n8k16 (R14-proven, TN=128). CSR edge aggregation.
// Graph pooling fused into the GEMM2 epilogue (atomicAdd to L2-resident pooled).
// ---------------------------------------------------------------------------

#define MAXN 200000
#define MAXE 800000
#define MAXG 8000
#define DIM  300
#define HID  600
#define NLAYER 5
#define EPS_BN 1e-5f
#define C4 75            // DIM / 4
#define KPAD1 304        // DIM padded to 16
#define KPAD2 608        // HID padded to 16
#define SCAN_B 256

__device__ __align__(256) float g_h     [(size_t)MAXN * DIM];
__device__ __align__(256) float g_aggr  [(size_t)MAXN * DIM];
__device__ __align__(256) float g_hid   [(size_t)MAXN * HID];
__device__ __align__(256) float g_post  [(size_t)MAXN * DIM];
__device__ __align__(256) float g_vfeat [(size_t)MAXG * DIM];
__device__ __align__(256) float g_pooled[(size_t)MAXG * DIM];
__device__ __align__(256) float g_vhid  [(size_t)MAXG * HID];
__device__ __align__(256) float g_cnt   [MAXG];
// CSR scratch
__device__ __align__(256) int g_deg     [MAXN];
__device__ __align__(256) int g_rowstart[MAXN + 1];
__device__ __align__(256) int g_cursor  [MAXN];
__device__ __align__(256) int g_btot    [1024];
__device__ __align__(256) int g_eid     [MAXE];
// bf16 hi/lo split weights, transposed: [Nc][Kpad]
__device__ __align__(256) __nv_bfloat16 g_W1h [(size_t)NLAYER * HID * KPAD1];
__device__ __align__(256) __nv_bfloat16 g_W1l [(size_t)NLAYER * HID * KPAD1];
__device__ __align__(256) __nv_bfloat16 g_W2h [(size_t)NLAYER * DIM * KPAD2];
__device__ __align__(256) __nv_bfloat16 g_W2l [(size_t)NLAYER * DIM * KPAD2];
__device__ __align__(256) __nv_bfloat16 g_vW1h[(size_t)HID * KPAD1];
__device__ __align__(256) __nv_bfloat16 g_vW1l[(size_t)HID * KPAD1];
__device__ __align__(256) __nv_bfloat16 g_vW2h[(size_t)DIM * KPAD2];
__device__ __align__(256) __nv_bfloat16 g_vW2l[(size_t)DIM * KPAD2];

// ---------------------------------------------------------------------------
// CSR construction (once per call)
// ---------------------------------------------------------------------------
__global__ void deg_count_kernel(const int* __restrict__ dst, int* __restrict__ deg, int E) {
    int e = blockIdx.x * blockDim.x + threadIdx.x;
    if (e < E) atomicAdd(&deg[dst[e]], 1);
}

__global__ void scan_block_kernel(const int* __restrict__ deg, int* __restrict__ rs,
                                  int* __restrict__ btot, int N) {
    __shared__ int s[SCAN_B];
    int i = blockIdx.x * SCAN_B + threadIdx.x;
    int v = (i < N) ? deg[i] : 0;
    s[threadIdx.x] = v;
    __syncthreads();
#pragma unroll
    for (int off = 1; off < SCAN_B; off <<= 1) {
        int t = (threadIdx.x >= off) ? s[threadIdx.x - off] : 0;
        __syncthreads();
        s[threadIdx.x] += t;
        __syncthreads();
    }
    if (i < N) rs[i] = s[threadIdx.x] - v;
    if (threadIdx.x == SCAN_B - 1) btot[blockIdx.x] = s[threadIdx.x];
}

__global__ void scan_total_kernel(int* __restrict__ btot, int nb) {
    __shared__ int s[1024];
    int v = (threadIdx.x < nb) ? btot[threadIdx.x] : 0;
    s[threadIdx.x] = v;
    __syncthreads();
#pragma unroll
    for (int off = 1; off < 1024; off <<= 1) {
        int t = (threadIdx.x >= off) ? s[threadIdx.x - off] : 0;
        __syncthreads();
        s[threadIdx.x] += t;
        __syncthreads();
    }
    if (threadIdx.x < nb) btot[threadIdx.x] = s[threadIdx.x] - v;
}

__global__ void add_offsets_kernel(int* __restrict__ rs, const int* __restrict__ btot,
                                   int N, int E) {
    int i = blockIdx.x * blockDim.x + threadIdx.x;
    if (i < N) rs[i] += btot[i / SCAN_B];
    if (i == 0) rs[N] = E;
}

__global__ void scatter_kernel(const int* __restrict__ dst, int* __restrict__ cursor,
                               int* __restrict__ eid, int E) {
    int e = blockIdx.x * blockDim.x + threadIdx.x;
    if (e >= E) return;
    int p = atomicAdd(&cursor[dst[e]], 1);
    eid[p] = e;
}

// ---------------------------------------------------------------------------
// Elementwise kernels
// ---------------------------------------------------------------------------
__global__ void atom_encode_kernel(const int* __restrict__ x,
                                   const float* __restrict__ atom_emb,
                                   float* __restrict__ h, int N) {
    int idx = blockIdx.x * blockDim.x + threadIdx.x;
    if (idx >= N * C4) return;
    int n = idx / C4;
    int c = (idx - n * C4) * 4;
    float4 s = make_float4(0.f, 0.f, 0.f, 0.f);
#pragma unroll
    for (int f = 0; f < 9; f++) {
        int v = x[n * 9 + f];
        const float4 e = *(const float4*)(atom_emb + ((size_t)(f * 64 + v)) * DIM + c);
        s.x += e.x; s.y += e.y; s.z += e.z; s.w += e.w;
    }
    *(float4*)(h + (size_t)n * DIM + c) = s;
}

__global__ void edge_aggr_csr(const float* __restrict__ h,
                              const int* __restrict__ src,
                              const int* __restrict__ ea,
                              const float* __restrict__ bond_l,
                              const int* __restrict__ rs,
                              const int* __restrict__ eid,
                              float* __restrict__ aggr, int N) {
    int idx = blockIdx.x * blockDim.x + threadIdx.x;
    if (idx >= N * C4) return;
    int n = idx / C4;
    int c = (idx - n * C4) * 4;
    float4 s = *(const float4*)(h + (size_t)n * DIM + c);
    int b = rs[n], en = rs[n + 1];
    for (int i = b; i < en; i++) {
        int e  = eid[i];
        int sn = src[e];
        int a0 = ea[e * 3 + 0], a1 = ea[e * 3 + 1], a2 = ea[e * 3 + 2];
        const float4 b0 = *(const float4*)(bond_l + ((size_t)(0 * 16 + a0)) * DIM + c);
        const float4 b1 = *(const float4*)(bond_l + ((size_t)(1 * 16 + a1)) * DIM + c);
        const float4 b2 = *(const float4*)(bond_l + ((size_t)(2 * 16 + a2)) * DIM + c);
        const float4 hv = *(const float4*)(h + (size_t)sn * DIM + c);
        s.x += fmaxf(hv.x + b0.x + b1.x + b2.x, 0.f);
        s.y += fmaxf(hv.y + b0.y + b1.y + b2.y, 0.f);
        s.z += fmaxf(hv.z + b0.z + b1.z + b2.z, 0.f);
        s.w += fmaxf(hv.w + b0.w + b1.w + b2.w, 0.f);
    }
    *(float4*)(aggr + (size_t)n * DIM + c) = s;
}

__global__ void add_vfeat_kernel(const float* __restrict__ post,
                                 const float* __restrict__ vfeat,
                                 const int* __restrict__ batch,
                                 float* __restrict__ h, int N) {
    int idx = blockIdx.x * blockDim.x + threadIdx.x;
    if (idx >= N * C4) return;
    int n = idx / C4;
    int c = (idx - n * C4) * 4;
    int g = batch[n];
    const float4 p = *(const float4*)(post  + (size_t)n * DIM + c);
    const float4 v = *(const float4*)(vfeat + (size_t)g * DIM + c);
    float4 o = make_float4(p.x + v.x, p.y + v.y, p.z + v.z, p.w + v.w);
    *(float4*)(h + (size_t)n * DIM + c) = o;
}

__global__ void count_kernel(const int* __restrict__ batch, float* __restrict__ cnt, int N) {
    int i = blockIdx.x * blockDim.x + threadIdx.x;
    if (i < N) atomicAdd(&cnt[batch[i]], 1.0f);
}

__global__ void vfeat_init_kernel(const float* __restrict__ vn, float* __restrict__ vfeat, int G) {
    int idx = blockIdx.x * blockDim.x + threadIdx.x;
    if (idx >= G * DIM) return;
    vfeat[idx] = vn[idx % DIM];
}

__global__ void copy_kernel(const float* __restrict__ src, float* __restrict__ dst, int n4) {
    int idx = blockIdx.x * blockDim.x + threadIdx.x;
    if (idx >= n4) return;
    *(float4*)(dst + idx * 4) = *(const float4*)(src + idx * 4);
}

__global__ void out_kernel(const float* __restrict__ pooled, const float* __restrict__ cnt,
                           float* __restrict__ out, int G) {
    int idx = blockIdx.x * blockDim.x + threadIdx.x;
    if (idx >= G * DIM) return;
    int g = idx / DIM;
    out[idx] = pooled[idx] / fmaxf(cnt[g], 1.0f);
}

__global__ void split_w_t(const float* __restrict__ W, __nv_bfloat16* __restrict__ Wh,
                          __nv_bfloat16* __restrict__ Wl, int K, int Nc, int Kpad) {
    int idx = blockIdx.x * blockDim.x + threadIdx.x;
    if (idx >= Nc * Kpad) return;
    int n = idx / Kpad;
    int k = idx - n * Kpad;
    float v = (k < K) ? W[(size_t)k * Nc + n] : 0.f;
    __nv_bfloat16 hh = __float2bfloat16_rn(v);
    __nv_bfloat16 ll = __float2bfloat16_rn(v - __bfloat162float(hh));
    Wh[idx] = hh;
    Wl[idx] = ll;
}

// ---------------------------------------------------------------------------
// bf16x3 GEMM with fused BN(+ReLU) epilogue and optional fused graph pooling.
// C = epi(A @ W + bias). A:[M,K] fp32 rm; Wh/Wl:[Nc][Kpad] bf16 K-major.
// If do_pool: pooled[batch[row]][col] += epi value (pooled pre-initialized).
// 128x128 tile, K-tile 16, 256 threads (8 warps 4x2), warp 32x64, m16n8k16.
// ---------------------------------------------------------------------------
#define GBM 128
#define GBN 128
#define LDA 20
#define LDBH 24

__device__ __forceinline__ void cp_async16(uint32_t saddr, const void* gptr, int src_bytes) {
    asm volatile("cp.async.cg.shared.global [%0], [%1], 16, %2;\n"
                 :: "r"(saddr), "l"(gptr), "r"(src_bytes));
}
__device__ __forceinline__ void cp_commit() { asm volatile("cp.async.commit_group;\n" ::); }
template <int N>
__device__ __forceinline__ void cp_wait() { asm volatile("cp.async.wait_group %0;\n" :: "n"(N)); }

__device__ __forceinline__ void mma_bf16(float* d, const uint32_t* a, const uint32_t* b) {
    asm volatile(
        "mma.sync.aligned.m16n8k16.row.col.f32.bf16.bf16.f32 "
        "{%0,%1,%2,%3}, {%4,%5,%6,%7}, {%8,%9}, {%0,%1,%2,%3};\n"
        : "+f"(d[0]), "+f"(d[1]), "+f"(d[2]), "+f"(d[3])
        : "r"(a[0]), "r"(a[1]), "r"(a[2]), "r"(a[3]), "r"(b[0]), "r"(b[1]));
}

__device__ __forceinline__ void split_pack(float2 v, uint32_t& hi, uint32_t& lo) {
    __nv_bfloat16 hx = __float2bfloat16_rn(v.x), hy = __float2bfloat16_rn(v.y);
    __nv_bfloat16 lx = __float2bfloat16_rn(v.x - __bfloat162float(hx));
    __nv_bfloat16 ly = __float2bfloat16_rn(v.y - __bfloat162float(hy));
    __nv_bfloat162 H = __halves2bfloat162(hx, hy);
    __nv_bfloat162 L = __halves2bfloat162(lx, ly);
    hi = *(uint32_t*)&H;
    lo = *(uint32_t*)&L;
}

__global__ __launch_bounds__(256) void gemm_bf16x3_bn(
    const float* __restrict__ A, const __nv_bfloat16* __restrict__ Bh,
    const __nv_bfloat16* __restrict__ Bl,
    const float* __restrict__ bias, const float* __restrict__ bnp,
    float* __restrict__ C,
    const int* __restrict__ batch, float* __restrict__ pooled, int do_pool,
    int M, int K, int Kpad, int Nc, int do_relu) {

    __shared__ __align__(16) float         As [2][GBM][LDA];
    __shared__ __align__(16) __nv_bfloat16 BsH[2][GBN][LDBH];
    __shared__ __align__(16) __nv_bfloat16 BsL[2][GBN][LDBH];

    const int tid = threadIdx.x;
    const int w = tid >> 5, l = tid & 31;
    const int wm = (w & 3) * 32;
    const int wn = (w >> 2) * 64;
    const int m0 = blockIdx.y * GBM;
    const int n0 = blockIdx.x * GBN;
    const int iters = (K + 15) / 16;

    const int qr = l >> 2;
    const int qc = l & 3;

    const int a_row = tid >> 2;
    const int a_kc  = (tid & 3) * 4;
    const int b_row = tid >> 1;
    const int b_ck  = (tid & 1) * 8;
    const bool brok = (n0 + b_row) < Nc;
    const __nv_bfloat16* BhRow = Bh + (size_t)(brok ? n0 + b_row : 0) * Kpad;
    const __nv_bfloat16* BlRow = Bl + (size_t)(brok ? n0 + b_row : 0) * Kpad;

    float acc[2][8][4];
#pragma unroll
    for (int mi = 0; mi < 2; mi++)
#pragma unroll
        for (int ni = 0; ni < 8; ni++)
#pragma unroll
            for (int r = 0; r < 4; r++) acc[mi][ni][r] = 0.f;

    auto issue_load = [&](int it, int buf) {
        const int k0 = it * 16;
#pragma unroll
        for (int i = 0; i < 2; i++) {
            int row = a_row + i * 64;
            int gm = m0 + row, gk = k0 + a_kc;
            int ok = (gm < M) && (gk + 4 <= K);
            const float* src = A + (size_t)(ok ? gm : 0) * K + (ok ? gk : 0);
            uint32_t dst = (uint32_t)__cvta_generic_to_shared(&As[buf][row][a_kc]);
            cp_async16(dst, src, ok ? 16 : 0);
        }
        {
            uint32_t dsth = (uint32_t)__cvta_generic_to_shared(&BsH[buf][b_row][b_ck]);
            uint32_t dstl = (uint32_t)__cvta_generic_to_shared(&BsL[buf][b_row][b_ck]);
            cp_async16(dsth, BhRow + k0 + b_ck, brok ? 16 : 0);
            cp_async16(dstl, BlRow + k0 + b_ck, brok ? 16 : 0);
        }
        cp_commit();
    };

    issue_load(0, 0);

    for (int it = 0; it < iters; it++) {
        const int buf = it & 1;
        if (it + 1 < iters) {
            issue_load(it + 1, buf ^ 1);
            cp_wait<1>();
        } else {
            cp_wait<0>();
        }
        __syncthreads();

        uint32_t ah[2][4], al[2][4];
#pragma unroll
        for (int mi = 0; mi < 2; mi++) {
            int r0 = wm + mi * 16 + qr;
            split_pack(*(float2*)&As[buf][r0][2 * qc],         ah[mi][0], al[mi][0]);
            split_pack(*(float2*)&As[buf][r0 + 8][2 * qc],     ah[mi][1], al[mi][1]);
            split_pack(*(float2*)&As[buf][r0][2 * qc + 8],     ah[mi][2], al[mi][2]);
            split_pack(*(float2*)&As[buf][r0 + 8][2 * qc + 8], ah[mi][3], al[mi][3]);
        }
        uint32_t bh[8][2], bl[8][2];
#pragma unroll
        for (int ni = 0; ni < 8; ni++) {
            int n = wn + ni * 8 + qr;
            bh[ni][0] = *(const uint32_t*)&BsH[buf][n][2 * qc];
            bh[ni][1] = *(const uint32_t*)&BsH[buf][n][2 * qc + 8];
            bl[ni][0] = *(const uint32_t*)&BsL[buf][n][2 * qc];
            bl[ni][1] = *(const uint32_t*)&BsL[buf][n][2 * qc + 8];
        }
#pragma unroll
        for (int mi = 0; mi < 2; mi++)
#pragma unroll
            for (int ni = 0; ni < 8; ni++) {
                mma_bf16(acc[mi][ni], ah[mi], bl[ni]);
                mma_bf16(acc[mi][ni], al[mi], bh[ni]);
                mma_bf16(acc[mi][ni], ah[mi], bh[ni]);
            }
        __syncthreads();
    }

    // -------- epilogue: bias -> BN -> (ReLU) -> store (+fused pool) --------
    int grow[2][2];
    if (do_pool) {
#pragma unroll
        for (int mi = 0; mi < 2; mi++)
#pragma unroll
            for (int r = 0; r < 2; r++) {
                int row = m0 + wm + mi * 16 + qr + r * 8;
                grow[mi][r] = (row < M) ? batch[row] : 0;
            }
    }
#pragma unroll
    for (int ni = 0; ni < 8; ni++) {
        int col = n0 + wn + ni * 8 + qc * 2;
        if (col >= Nc) continue;
        float bb0 = bias[col], bb1 = bias[col + 1];
        float ga0 = bnp[col],          be0 = bnp[Nc + col];
        float mu0 = bnp[2 * Nc + col], va0 = bnp[3 * Nc + col];
        float ga1 = bnp[col + 1],          be1 = bnp[Nc + col + 1];
        float mu1 = bnp[2 * Nc + col + 1], va1 = bnp[3 * Nc + col + 1];
        float s0 = ga0 * rsqrtf(va0 + EPS_BN), t0 = be0 - mu0 * s0;
        float s1 = ga1 * rsqrtf(va1 + EPS_BN), t1 = be1 - mu1 * s1;
#pragma unroll
        for (int mi = 0; mi < 2; mi++) {
#pragma unroll
            for (int r = 0; r < 2; r++) {
                int row = m0 + wm + mi * 16 + qr + r * 8;
                if (row >= M) continue;
                float v0 = (acc[mi][ni][r * 2 + 0] + bb0) * s0 + t0;
                float v1 = (acc[mi][ni][r * 2 + 1] + bb1) * s1 + t1;
                if (do_relu) { v0 = fmaxf(v0, 0.f); v1 = fmaxf(v1, 0.f); }
                *(float2*)(C + (size_t)row * Nc + col) = make_float2(v0, v1);
                if (do_pool) {
                    float* q = pooled + (size_t)grow[mi][r] * Nc + col;
                    atomicAdd(q + 0, v0);
                    atomicAdd(q + 1, v1);
                }
            }
        }
    }
}

static void run_gemm(const float* A, const __nv_bfloat16* Bh, const __nv_bfloat16* Bl,
                     const float* bias, const float* bnp, float* C,
                     const int* batch, float* pooled, int do_pool,
                     int M, int K, int Kpad, int Nc, int do_relu) {
    dim3 grid((Nc + GBN - 1) / GBN, (M + GBM - 1) / GBM);
    gemm_bf16x3_bn<<<grid, 256>>>(A, Bh, Bl, bias, bnp, C, batch, pooled, do_pool,
                                  M, K, Kpad, Nc, do_relu);
}

// ---------------------------------------------------------------------------
// kernel_launch
// ---------------------------------------------------------------------------
extern "C" void kernel_launch(void* const* d_in, const int* in_sizes, int n_in,
                              void* d_out, int out_size) {
    const int*   x         = (const int*)  d_in[0];
    const int*   edge_idx  = (const int*)  d_in[1];
    const int*   edge_attr = (const int*)  d_in[2];
    const int*   batch     = (const int*)  d_in[3];
    const float* atom_emb  = (const float*)d_in[4];
    const float* bond_emb  = (const float*)d_in[5];
    const float* W1        = (const float*)d_in[6];
    const float* b1        = (const float*)d_in[7];
    const float* bn_in     = (const float*)d_in[8];
    const float* W2        = (const float*)d_in[9];
    const float* b2        = (const float*)d_in[10];
    const float* bn_out    = (const float*)d_in[11];
    const float* vn        = (const float*)d_in[12];
    const float* vW1       = (const float*)d_in[13];
    const float* vb1       = (const float*)d_in[14];
    const float* vbn1      = (const float*)d_in[15];
    const float* vW2       = (const float*)d_in[16];
    const float* vb2       = (const float*)d_in[17];
    const float* vbn2      = (const float*)d_in[18];
    float*       out       = (float*)d_out;

    const int N = in_sizes[0] / 9;
    const int E = in_sizes[1] / 2;
    const int G = out_size / DIM;

    float *h, *aggr, *hid, *post, *vfeat, *pooled, *vhid, *cnt;
    int *deg, *rowstart, *cursor, *btot, *eid;
    __nv_bfloat16 *W1h, *W1l, *W2h, *W2l, *vW1h, *vW1l, *vW2h, *vW2l;
    cudaGetSymbolAddress((void**)&h,        g_h);
    cudaGetSymbolAddress((void**)&aggr,     g_aggr);
    cudaGetSymbolAddress((void**)&hid,      g_hid);
    cudaGetSymbolAddress((void**)&post,     g_post);
    cudaGetSymbolAddress((void**)&vfeat,    g_vfeat);
    cudaGetSymbolAddress((void**)&pooled,   g_pooled);
    cudaGetSymbolAddress((void**)&vhid,     g_vhid);
    cudaGetSymbolAddress((void**)&cnt,      g_cnt);
    cudaGetSymbolAddress((void**)&deg,      g_deg);
    cudaGetSymbolAddress((void**)&rowstart, g_rowstart);
    cudaGetSymbolAddress((void**)&cursor,   g_cursor);
    cudaGetSymbolAddress((void**)&btot,     g_btot);
    cudaGetSymbolAddress((void**)&eid,      g_eid);
    cudaGetSymbolAddress((void**)&W1h,      g_W1h);
    cudaGetSymbolAddress((void**)&W1l,      g_W1l);
    cudaGetSymbolAddress((void**)&W2h,      g_W2h);
    cudaGetSymbolAddress((void**)&W2l,      g_W2l);
    cudaGetSymbolAddress((void**)&vW1h,     g_vW1h);
    cudaGetSymbolAddress((void**)&vW1l,     g_vW1l);
    cudaGetSymbolAddress((void**)&vW2h,     g_vW2h);
    cudaGetSymbolAddress((void**)&vW2l,     g_vW2l);

    const int* src = edge_idx;
    const int* dst = edge_idx + E;

    const int TPB = 256;
    const int nodeC4Blocks = (N * C4 + TPB - 1) / TPB;
    const int scanBlocks = (N + SCAN_B - 1) / SCAN_B;

    // ---- CSR build (once) ----
    cudaMemsetAsync(deg, 0, (size_t)N * sizeof(int));
    deg_count_kernel<<<(E + TPB - 1) / TPB, TPB>>>(dst, deg, E);
    scan_block_kernel<<<scanBlocks, SCAN_B>>>(deg, rowstart, btot, N);
    scan_total_kernel<<<1, 1024>>>(btot, scanBlocks);
    add_offsets_kernel<<<(N + TPB - 1) / TPB, TPB>>>(rowstart, btot, N, E);
    cudaMemcpyAsync(cursor, rowstart, (size_t)N * sizeof(int), cudaMemcpyDeviceToDevice);
    scatter_kernel<<<(E + TPB - 1) / TPB, TPB>>>(dst, cursor, eid, E);

    // ---- weight prep ----
    {
        int t1 = HID * KPAD1;
        int t2 = DIM * KPAD2;
        for (int l = 0; l < NLAYER; l++) {
            split_w_t<<<(t1 + TPB - 1) / TPB, TPB>>>(
                W1 + (size_t)l * DIM * HID, W1h + (size_t)l * t1, W1l + (size_t)l * t1,
                DIM, HID, KPAD1);
            split_w_t<<<(t2 + TPB - 1) / TPB, TPB>>>(
                W2 + (size_t)l * HID * DIM, W2h + (size_t)l * t2, W2l + (size_t)l * t2,
                HID, DIM, KPAD2);
        }
        split_w_t<<<(t1 + TPB - 1) / TPB, TPB>>>(vW1, vW1h, vW1l, DIM, HID, KPAD1);
        split_w_t<<<(t2 + TPB - 1) / TPB, TPB>>>(vW2, vW2h, vW2l, HID, DIM, KPAD2);
    }

    atom_encode_kernel<<<nodeC4Blocks, TPB>>>(x, atom_emb, h, N);
    vfeat_init_kernel<<<(G * DIM + TPB - 1) / TPB, TPB>>>(vn, vfeat, G);
    cudaMemsetAsync(cnt, 0, (size_t)G * sizeof(float));
    count_kernel<<<(N + TPB - 1) / TPB, TPB>>>(batch, cnt, N);

    for (int l = 0; l < NLAYER; l++) {
        if (l > 0)
            add_vfeat_kernel<<<nodeC4Blocks, TPB>>>(post, vfeat, batch, h, N);

        edge_aggr_csr<<<nodeC4Blocks, TPB>>>(
            h, src, edge_attr, bond_emb + (size_t)l * 3 * 16 * DIM,
            rowstart, eid, aggr, N);

        // hid = relu(bn_in(z @ W1 + b1))
        run_gemm(aggr, W1h + (size_t)l * HID * KPAD1, W1l + (size_t)l * HID * KPAD1,
                 b1 + (size_t)l * HID, bn_in + (size_t)l * 4 * HID, hid,
                 nullptr, nullptr, 0, N, DIM, KPAD1, HID, 1);

        // prepare pooled BEFORE GEMM2 when pooling is fused into its epilogue
        const int vn_layer = (l >= 1 && l < NLAYER - 1);
        if (vn_layer)
            copy_kernel<<<(G * C4 + TPB - 1) / TPB, TPB>>>(vfeat, pooled, G * C4);
        else if (l == NLAYER - 1)
            cudaMemsetAsync(pooled, 0, (size_t)G * DIM * sizeof(float));

        // post = bn_out(hid @ W2 + b2) (+relu except last); pool fused for l>=1
        run_gemm(hid, W2h + (size_t)l * DIM * KPAD2, W2l + (size_t)l * DIM * KPAD2,
                 b2 + (size_t)l * DIM, bn_out + (size_t)l * 4 * DIM, post,
                 batch, pooled, (l >= 1) ? 1 : 0,
                 N, HID, KPAD2, DIM, (l < NLAYER - 1) ? 1 : 0);

        if (vn_layer) {
            run_gemm(pooled, vW1h, vW1l, vb1, vbn1, vhid,
                     nullptr, nullptr, 0, G, DIM, KPAD1, HID, 1);
            run_gemm(vhid, vW2h, vW2l, vb2, vbn2, vfeat,
                     nullptr, nullptr, 0, G, HID, KPAD2, DIM, 1);
        }
    }

    out_kernel<<<(G * DIM + TPB - 1) / TPB, TPB>>>(pooled, cnt, out, G);
}